// round 13
// baseline (speedup 1.0000x reference)
#include <cuda_runtime.h>
#include <cuda_fp16.h>
#include <cstdint>

// Fused QKV projection + RoPE + transpose — fp16 HMMA m16n8k16.
// Pass 1 (single kernel, MLP=4): f32 -> f16 scratch (X16, W16 concat).
// Pass 2: C[16384,6144] = Xh . Wh^T. CTA 128x128xK64, 256 thr, 8 warps,
//         32x64 warp tiles (regs=128 -> 2 CTAs/SM), 3-stage cp.async ring,
//         one barrier per k-tile, ldmatrix, fused RoPE epilogue.
// (Resubmit — previous bench aborted on container infra.)

#define BM 128
#define BN 128
#define NT 64
#define STAGES 3
#define A_BYTES (BM * 128)     // 16384
#define B_BYTES (BN * 128)     // 16384
#define STAGE_BYTES (A_BYTES + B_BYTES)
#define SMEM_TOTAL (STAGES * STAGE_BYTES)   // 98304

__device__ __align__(16) __half X16[67108864];   // [16384][4096]
__device__ __align__(16) __half W16[25165824];   // [6144][4096]

// 16 elements per thread, 4 independent 16B loads (MLP=4) to cover DRAM
// latency. Tensor boundaries are all multiples of 16.
__global__ __launch_bounds__(256) void cvt_all(
    const float* __restrict__ x,  const float* __restrict__ wq,
    const float* __restrict__ wk, const float* __restrict__ wv)
{
    const size_t i = ((size_t)blockIdx.x * 256 + threadIdx.x) * 16;
    const float* src;
    __half* dst;
    if (i < 67108864UL)       { src = x  + i;               dst = X16 + i; }
    else if (i < 83886080UL)  { src = wq + (i - 67108864);  dst = W16 + (i - 67108864); }
    else if (i < 88080384UL)  { src = wk + (i - 83886080);  dst = W16 + 16777216 + (i - 83886080); }
    else                      { src = wv + (i - 88080384);  dst = W16 + 20971520 + (i - 88080384); }

    float4 f0 = __ldcs(reinterpret_cast<const float4*>(src));
    float4 f1 = __ldcs(reinterpret_cast<const float4*>(src) + 1);
    float4 f2 = __ldcs(reinterpret_cast<const float4*>(src) + 2);
    float4 f3 = __ldcs(reinterpret_cast<const float4*>(src) + 3);

    union { uint4 u; __half2 h[4]; } p0, p1;
    p0.h[0] = __floats2half2_rn(f0.x, f0.y);
    p0.h[1] = __floats2half2_rn(f0.z, f0.w);
    p0.h[2] = __floats2half2_rn(f1.x, f1.y);
    p0.h[3] = __floats2half2_rn(f1.z, f1.w);
    p1.h[0] = __floats2half2_rn(f2.x, f2.y);
    p1.h[1] = __floats2half2_rn(f2.z, f2.w);
    p1.h[2] = __floats2half2_rn(f3.x, f3.y);
    p1.h[3] = __floats2half2_rn(f3.z, f3.w);

    reinterpret_cast<uint4*>(dst)[0] = p0.u;
    reinterpret_cast<uint4*>(dst)[1] = p1.u;
}

__device__ __forceinline__ uint32_t s2u(const void* p) {
    uint32_t a;
    asm("{ .reg .u64 t; cvta.to.shared.u64 t, %1; cvt.u32.u64 %0, t; }"
        : "=r"(a) : "l"(p));
    return a;
}

__global__ __launch_bounds__(256, 2) void qkv_hmma(
    const float* __restrict__ cosT,
    const float* __restrict__ sinT,
    float* __restrict__ out)
{
    extern __shared__ char smem[];
    const uint32_t sb = s2u(smem);
    const int tid = threadIdx.x;
    const int bn  = blockIdx.x;       // 0..47 head block
    const int bm  = blockIdx.y;       // 0..127 row block
    const int m0  = bm * BM;
    const int gn0 = bn * BN;

    int kind;
    if (bn < 32) kind = 0; else if (bn < 40) kind = 1; else kind = 2;

    const int warp = tid >> 5;
    const int lane = tid & 31;
    const int wm   = warp >> 1;       // 0..3 -> m = wm*32
    const int wn   = warp & 1;        // 0..1 -> n = wn*64
    const int q8   = lane >> 3;
    const int lr   = lane & 7;

    float acc[2][8][4];
    #pragma unroll
    for (int i = 0; i < 2; i++)
        #pragma unroll
        for (int j = 0; j < 8; j++)
            #pragma unroll
            for (int k = 0; k < 4; k++) acc[i][j][k] = 0.f;

    // ---- loader: 2048 chunks of 16B per stage, 8 per thread ----
    auto load_tile = [&](int kt, int s) {
        const uint32_t base = sb + s * STAGE_BYTES;
        #pragma unroll
        for (int j = 0; j < 8; j++) {
            const int c = tid + j * 256;
            if (c < 1024) {                          // A: 128 rows x 8 chunks
                const int row = c >> 3, ch = c & 7;
                const uint32_t dst = base + row * 128 + ((ch ^ (row & 7)) << 4);
                const __half* src = X16 + (size_t)(m0 + row) * 4096 + kt * 64 + ch * 8;
                asm volatile("cp.async.cg.shared.global [%0], [%1], 16;\n"
                             :: "r"(dst), "l"(src));
            } else {                                 // B: 128 rows x 8 chunks
                const int cb = c - 1024;
                const int row = cb >> 3, ch = cb & 7;
                const uint32_t dst = base + A_BYTES + row * 128 + ((ch ^ (row & 7)) << 4);
                const __half* src = W16 + (size_t)(gn0 + row) * 4096 + kt * 64 + ch * 8;
                asm volatile("cp.async.cg.shared.global [%0], [%1], 16;\n"
                             :: "r"(dst), "l"(src));
            }
        }
        asm volatile("cp.async.commit_group;\n");
    };

    load_tile(0, 0);
    load_tile(1, 1);

    int sl = 2;                       // next stage slot to fill
    for (int kt = 0; kt < NT; kt++) {
        asm volatile("cp.async.wait_group 1;\n");
        __syncthreads();
        // slot sl == (kt-1)%3: its consumer finished before the barrier. Safe.
        if (kt + 2 < NT) load_tile(kt + 2, sl);
        else asm volatile("cp.async.commit_group;\n");
        sl = (sl == 2) ? 0 : sl + 1;

        const uint32_t Ab = sb + (kt % 3) * STAGE_BYTES;
        const uint32_t Bb = Ab + A_BYTES;

        #pragma unroll
        for (int ks = 0; ks < 4; ks++) {
            uint32_t a[2][4];
            #pragma unroll
            for (int mm = 0; mm < 2; mm++) {
                const int row = wm * 32 + mm * 16 + (q8 & 1) * 8 + lr;
                const int ch  = ks * 2 + (q8 >> 1);
                const uint32_t addr = Ab + row * 128 + ((ch ^ (row & 7)) << 4);
                asm volatile("ldmatrix.sync.aligned.m8n8.x4.shared.b16 "
                             "{%0,%1,%2,%3}, [%4];"
                             : "=r"(a[mm][0]), "=r"(a[mm][1]),
                               "=r"(a[mm][2]), "=r"(a[mm][3]) : "r"(addr));
            }
            uint32_t b[8][2];
            #pragma unroll
            for (int nb = 0; nb < 8; nb += 2) {
                const int row = wn * 64 + nb * 8 + (q8 >> 1) * 8 + lr;
                const int ch  = ks * 2 + (q8 & 1);
                const uint32_t addr = Bb + row * 128 + ((ch ^ (row & 7)) << 4);
                asm volatile("ldmatrix.sync.aligned.m8n8.x4.shared.b16 "
                             "{%0,%1,%2,%3}, [%4];"
                             : "=r"(b[nb][0]), "=r"(b[nb][1]),
                               "=r"(b[nb + 1][0]), "=r"(b[nb + 1][1]) : "r"(addr));
            }
            #pragma unroll
            for (int mm = 0; mm < 2; mm++)
                #pragma unroll
                for (int nn = 0; nn < 8; nn++) {
                    asm volatile(
                        "mma.sync.aligned.m16n8k16.row.col.f32.f16.f16.f32 "
                        "{%0,%1,%2,%3}, {%4,%5,%6,%7}, {%8,%9}, {%0,%1,%2,%3};\n"
                        : "+f"(acc[mm][nn][0]), "+f"(acc[mm][nn][1]),
                          "+f"(acc[mm][nn][2]), "+f"(acc[mm][nn][3])
                        : "r"(a[mm][0]), "r"(a[mm][1]),
                          "r"(a[mm][2]), "r"(a[mm][3]),
                          "r"(b[nn][0]), "r"(b[nn][1]));
                }
        }
    }

    // ---- epilogue: RoPE (q,k) + transposed store ----
    const int bb     = m0 >> 12;
    const int s_base = m0 & 4095;
    long obase;
    if (kind == 0)      obase = ((long)(bb * 32 + bn)) << 19;
    else if (kind == 1) obase = 67108864L + (((long)(bb * 8 + bn - 32)) << 19);
    else                obase = 83886080L + (((long)(bb * 8 + bn - 40)) << 19);

    const int l4 = lane & 3;
    #pragma unroll
    for (int mm = 0; mm < 2; mm++) {
        #pragma unroll
        for (int h = 0; h < 2; h++) {
            const int s = s_base + wm * 32 + mm * 16 + h * 8 + (lane >> 2);
            #pragma unroll
            for (int nn = 0; nn < 8; nn++) {
                const int d = wn * 64 + nn * 8 + 2 * l4;
                float v0 = acc[mm][nn][2 * h + 0];
                float v1 = acc[mm][nn][2 * h + 1];
                if (kind != 2) {
                    const int i = d >> 1;
                    const float c  = __ldg(cosT + s * 64 + i);
                    const float sn = __ldg(sinT + s * 64 + i);
                    const float r0 = v0 * c - v1 * sn;
                    const float r1 = v0 * sn + v1 * c;
                    v0 = r0; v1 = r1;
                }
                *reinterpret_cast<float2*>(out + obase + (long)s * 128 + d) =
                    make_float2(v0, v1);
            }
        }
    }
}

extern "C" void kernel_launch(void* const* d_in, const int* in_sizes, int n_in,
                              void* d_out, int out_size)
{
    (void)in_sizes; (void)n_in; (void)out_size;

    cvt_all<<<22528, 256>>>((const float*)d_in[0], (const float*)d_in[1],
                            (const float*)d_in[2], (const float*)d_in[3]);

    cudaFuncSetAttribute(qkv_hmma, cudaFuncAttributeMaxDynamicSharedMemorySize,
                         SMEM_TOTAL);
    dim3 grid(48, 128);
    qkv_hmma<<<grid, 256, SMEM_TOTAL>>>((const float*)d_in[4],
                                        (const float*)d_in[5],
                                        (float*)d_out);
}